// round 1
// baseline (speedup 1.0000x reference)
#include <cuda_runtime.h>
#include <math.h>

#define NPTS 16384  // 8 * 2048 points per cloud

// SoA-ish storage: float4 = (x, y, z, 0.5*||p||^2)
__device__ float4 g_pts[2][NPTS];

__global__ void prep_kernel(const float* __restrict__ pc1,
                            const float* __restrict__ pc2,
                            float* __restrict__ out) {
    int i = blockIdx.x * blockDim.x + threadIdx.x;
    if (i == 0) out[0] = 0.0f;   // d_out is poisoned; zero it before accumulation
    if (i < NPTS) {
        float x = pc1[3 * i + 0];
        float y = pc1[3 * i + 1];
        float z = pc1[3 * i + 2];
        g_pts[0][i] = make_float4(x, y, z, 0.5f * (x * x + y * y + z * z));
    } else if (i < 2 * NPTS) {
        int j = i - NPTS;
        float x = pc2[3 * j + 0];
        float y = pc2[3 * j + 1];
        float z = pc2[3 * j + 2];
        g_pts[1][j] = make_float4(x, y, z, 0.5f * (x * x + y * y + z * z));
    }
}

// 128 blocks x 256 threads. Blocks [0,64): queries = pc1, targets = pc2 (dist2).
// Blocks [64,128): queries = pc2, targets = pc1 (dist1).
// Each thread owns one query point; streams all 16384 targets via uniform
// (warp-broadcast) LDG.128 from L1/L2.
__global__ void __launch_bounds__(256, 1)
nn_kernel(float* __restrict__ out) {
    const int dir = (blockIdx.x >= 64) ? 1 : 0;
    const int qi  = (blockIdx.x & 63) * 256 + threadIdx.x;

    const float4* __restrict__ tgt = g_pts[dir ^ 1];
    const float4  q = g_pts[dir][qi];

    float smin = 3.0e38f;

    #pragma unroll 8
    for (int j = 0; j < NPTS; ++j) {
        const float4 b = tgt[j];
        // score = 0.5*||b||^2 - a.b   (argmin-equivalent to ||a-b||^2)
        float dot = fmaf(q.x, b.x, fmaf(q.y, b.y, q.z * b.z));
        float s   = b.w - dot;
        smin = fminf(smin, s);
    }

    // ||a-b||^2 = 2*(0.5||a||^2 + score)
    float d2 = 2.0f * (q.w + smin);
    float d  = sqrtf(fmaxf(d2, 0.0f));

    // Block reduction of d, then one atomicAdd per block.
    __shared__ float warp_sums[8];
    float v = d;
    #pragma unroll
    for (int off = 16; off > 0; off >>= 1)
        v += __shfl_xor_sync(0xFFFFFFFFu, v, off);
    const int lane = threadIdx.x & 31;
    const int wid  = threadIdx.x >> 5;
    if (lane == 0) warp_sums[wid] = v;
    __syncthreads();
    if (wid == 0) {
        float s = (lane < 8) ? warp_sums[lane] : 0.0f;
        #pragma unroll
        for (int off = 4; off > 0; off >>= 1)
            s += __shfl_xor_sync(0xFFFFFFFFu, s, off);
        if (lane == 0)
            atomicAdd(out, s * (1.0f / (float)NPTS));
    }
}

extern "C" void kernel_launch(void* const* d_in, const int* in_sizes, int n_in,
                              void* d_out, int out_size) {
    const float* pc1 = (const float*)d_in[0];
    const float* pc2 = (const float*)d_in[1];
    float* out = (float*)d_out;

    prep_kernel<<<(2 * NPTS + 255) / 256, 256>>>(pc1, pc2, out);
    nn_kernel<<<128, 256>>>(out);
}

// round 2
// speedup vs baseline: 4.2602x; 4.2602x over previous
#include <cuda_runtime.h>
#include <math.h>

#define NPTS   16384   // 8 * 2048 points per cloud
#define NPAIR  8192    // target pairs (2 targets packed per f32x2 lane-pair)
#define QPT    4       // queries per thread
#define THREADS 256
#define QPB    (THREADS * QPT)        // 1024 queries per block
#define QBLK   (NPTS / QPB)           // 16 query-blocks per direction
#define CHUNKS 9                      // target chunks -> 2*16*9 = 288 blocks
#define CPAIRS 911                    // ceil(8192/9)

// Pair-packed targets: A = (x0,x1,y0,y1), B = (z0,z1,w0,w1), w = 0.5*||p||^2
__device__ float4   g_packA[2][NPAIR];
__device__ float4   g_packB[2][NPAIR];
__device__ float4   g_q[2][NPTS];          // (x, y, z, 0.5*||p||^2)
__device__ unsigned g_minbits[2][NPTS];    // order-encoded float min

__device__ __forceinline__ unsigned enc_f32(float f) {
    unsigned u = __float_as_uint(f);
    return (u & 0x80000000u) ? ~u : (u | 0x80000000u);
}
__device__ __forceinline__ float dec_f32(unsigned e) {
    return (e & 0x80000000u) ? __uint_as_float(e & 0x7FFFFFFFu)
                             : __uint_as_float(~e);
}

__device__ __forceinline__ unsigned long long pack2(float lo, float hi) {
    unsigned long long r;
    asm("mov.b64 %0, {%1, %2};" : "=l"(r) : "f"(lo), "f"(hi));
    return r;
}
__device__ __forceinline__ unsigned long long fma2(unsigned long long a,
                                                   unsigned long long b,
                                                   unsigned long long c) {
    unsigned long long d;
    asm("fma.rn.f32x2 %0, %1, %2, %3;" : "=l"(d) : "l"(a), "l"(b), "l"(c));
    return d;
}

__global__ void prep_kernel(const float* __restrict__ pc1,
                            const float* __restrict__ pc2,
                            float* __restrict__ out) {
    int i = blockIdx.x * blockDim.x + threadIdx.x;   // pair index over both clouds
    if (i == 0) out[0] = 0.0f;
    if (i >= 2 * NPAIR) return;
    int c = (i >= NPAIR) ? 1 : 0;
    int j = i - c * NPAIR;
    const float* pc = c ? pc2 : pc1;

    float x0 = pc[6 * j + 0], y0 = pc[6 * j + 1], z0 = pc[6 * j + 2];
    float x1 = pc[6 * j + 3], y1 = pc[6 * j + 4], z1 = pc[6 * j + 5];
    float w0 = 0.5f * (x0 * x0 + y0 * y0 + z0 * z0);
    float w1 = 0.5f * (x1 * x1 + y1 * y1 + z1 * z1);

    g_packA[c][j] = make_float4(x0, x1, y0, y1);
    g_packB[c][j] = make_float4(z0, z1, w0, w1);
    g_q[c][2 * j + 0] = make_float4(x0, y0, z0, w0);
    g_q[c][2 * j + 1] = make_float4(x1, y1, z1, w1);
    g_minbits[c][2 * j + 0] = 0xFFFFFFFFu;
    g_minbits[c][2 * j + 1] = 0xFFFFFFFFu;
}

// Grid: 2 dirs * 16 query-blocks * 9 target-chunks = 288 blocks.
// Each thread owns 4 queries; per 2 targets (one packed pair): 12 FFMA2 + 8 FMNMX.
__global__ void __launch_bounds__(THREADS)
nn_kernel() {
    const int b     = blockIdx.x;
    const int dir   = b / (QBLK * CHUNKS);
    const int rem   = b % (QBLK * CHUNKS);
    const int qb    = rem / CHUNKS;
    const int chunk = rem % CHUNKS;

    const int js = chunk * CPAIRS;
    const int je = (js + CPAIRS < NPAIR) ? (js + CPAIRS) : NPAIR;

    const int tgt = dir ^ 1;
    const ulonglong2* __restrict__ pA =
        reinterpret_cast<const ulonglong2*>(g_packA[tgt]);
    const ulonglong2* __restrict__ pB =
        reinterpret_cast<const ulonglong2*>(g_packB[tgt]);

    // Per-thread query state: negated components, splat into both f32x2 lanes.
    unsigned long long nqx[QPT], nqy[QPT], nqz[QPT];
    int qidx[QPT];
    #pragma unroll
    for (int k = 0; k < QPT; ++k) {
        int qi = qb * QPB + k * THREADS + threadIdx.x;
        qidx[k] = qi;
        float4 q = g_q[dir][qi];
        nqx[k] = pack2(-q.x, -q.x);
        nqy[k] = pack2(-q.y, -q.y);
        nqz[k] = pack2(-q.z, -q.z);
    }

    float m0[QPT], m1[QPT];
    #pragma unroll
    for (int k = 0; k < QPT; ++k) { m0[k] = 3.0e38f; m1[k] = 3.0e38f; }

    #pragma unroll 2
    for (int j = js; j < je; ++j) {
        const ulonglong2 A = pA[j];   // A.x = (x0,x1), A.y = (y0,y1)
        const ulonglong2 B = pB[j];   // B.x = (z0,z1), B.y = (w0,w1)
        #pragma unroll
        for (int k = 0; k < QPT; ++k) {
            // score = w - q.b  (argmin-equivalent to ||q-b||^2), 2 targets at once
            unsigned long long acc = fma2(nqz[k], B.x, B.y);
            acc = fma2(nqy[k], A.y, acc);
            acc = fma2(nqx[k], A.x, acc);
            float2 s = *reinterpret_cast<float2*>(&acc);
            m0[k] = fminf(m0[k], s.x);
            m1[k] = fminf(m1[k], s.y);
        }
    }

    #pragma unroll
    for (int k = 0; k < QPT; ++k) {
        float s = fminf(m0[k], m1[k]);
        atomicMin(&g_minbits[dir][qidx[k]], enc_f32(s));
    }
}

__global__ void __launch_bounds__(256)
reduce_kernel(float* __restrict__ out) {
    const int i   = blockIdx.x * blockDim.x + threadIdx.x;   // 0 .. 32767
    const int dir = i >> 14;
    const int qi  = i & (NPTS - 1);

    float s  = dec_f32(g_minbits[dir][qi]);
    float qw = g_q[dir][qi].w;
    float d2 = 2.0f * (qw + s);
    float d  = sqrtf(fmaxf(d2, 0.0f));

    __shared__ float warp_sums[8];
    float v = d;
    #pragma unroll
    for (int off = 16; off > 0; off >>= 1)
        v += __shfl_xor_sync(0xFFFFFFFFu, v, off);
    const int lane = threadIdx.x & 31;
    const int wid  = threadIdx.x >> 5;
    if (lane == 0) warp_sums[wid] = v;
    __syncthreads();
    if (wid == 0) {
        float t = (lane < 8) ? warp_sums[lane] : 0.0f;
        #pragma unroll
        for (int off = 4; off > 0; off >>= 1)
            t += __shfl_xor_sync(0xFFFFFFFFu, t, off);
        if (lane == 0)
            atomicAdd(out, t * (1.0f / (float)NPTS));
    }
}

extern "C" void kernel_launch(void* const* d_in, const int* in_sizes, int n_in,
                              void* d_out, int out_size) {
    const float* pc1 = (const float*)d_in[0];
    const float* pc2 = (const float*)d_in[1];
    float* out = (float*)d_out;

    prep_kernel<<<(2 * NPAIR + 255) / 256, 256>>>(pc1, pc2, out);
    nn_kernel<<<2 * QBLK * CHUNKS, THREADS>>>();
    reduce_kernel<<<(2 * NPTS) / 256, 256>>>(out);
}

// round 3
// speedup vs baseline: 4.6158x; 1.0835x over previous
#include <cuda_runtime.h>
#include <math.h>

#define NPTS    16384   // 8 * 2048 points per cloud
#define NPAIR   8192    // target pairs (2 targets packed per f32x2 lane-pair)
#define QPT     8       // queries per thread
#define THREADS 256
#define QPB     (THREADS * QPT)        // 2048 queries per block
#define QBLK    (NPTS / QPB)           // 8 query-blocks per direction
#define CHUNKS  9                      // 2*8*9 = 144 blocks = one wave on 148 SMs
#define CPAIRS  911                    // ceil(8192/9)

// Pair-packed targets: A = (x0,x1,y0,y1), B = (z0,z1,w0,w1), w = 0.5*||p||^2
__device__ float4   g_packA[2][NPAIR];
__device__ float4   g_packB[2][NPAIR];
__device__ float4   g_q[2][NPTS];          // (x, y, z, 0.5*||p||^2)
__device__ unsigned g_minbits[2][NPTS];    // order-encoded float min

__device__ __forceinline__ unsigned enc_f32(float f) {
    unsigned u = __float_as_uint(f);
    return (u & 0x80000000u) ? ~u : (u | 0x80000000u);
}
__device__ __forceinline__ float dec_f32(unsigned e) {
    return (e & 0x80000000u) ? __uint_as_float(e & 0x7FFFFFFFu)
                             : __uint_as_float(~e);
}

__device__ __forceinline__ unsigned long long pack2(float lo, float hi) {
    unsigned long long r;
    asm("mov.b64 %0, {%1, %2};" : "=l"(r) : "f"(lo), "f"(hi));
    return r;
}
__device__ __forceinline__ unsigned long long fma2(unsigned long long a,
                                                   unsigned long long b,
                                                   unsigned long long c) {
    unsigned long long d;
    asm("fma.rn.f32x2 %0, %1, %2, %3;" : "=l"(d) : "l"(a), "l"(b), "l"(c));
    return d;
}

__global__ void prep_kernel(const float* __restrict__ pc1,
                            const float* __restrict__ pc2,
                            float* __restrict__ out) {
    int i = blockIdx.x * blockDim.x + threadIdx.x;   // pair index over both clouds
    if (i == 0) out[0] = 0.0f;
    if (i >= 2 * NPAIR) return;
    int c = (i >= NPAIR) ? 1 : 0;
    int j = i - c * NPAIR;
    const float* pc = c ? pc2 : pc1;

    float x0 = pc[6 * j + 0], y0 = pc[6 * j + 1], z0 = pc[6 * j + 2];
    float x1 = pc[6 * j + 3], y1 = pc[6 * j + 4], z1 = pc[6 * j + 5];
    float w0 = 0.5f * (x0 * x0 + y0 * y0 + z0 * z0);
    float w1 = 0.5f * (x1 * x1 + y1 * y1 + z1 * z1);

    g_packA[c][j] = make_float4(x0, x1, y0, y1);
    g_packB[c][j] = make_float4(z0, z1, w0, w1);
    g_q[c][2 * j + 0] = make_float4(x0, y0, z0, w0);
    g_q[c][2 * j + 1] = make_float4(x1, y1, z1, w1);
    g_minbits[c][2 * j + 0] = 0xFFFFFFFFu;
    g_minbits[c][2 * j + 1] = 0xFFFFFFFFu;
}

// Grid: 2 dirs * 8 query-blocks * 9 target-chunks = 144 blocks (single wave).
// Each thread owns 8 queries; per packed target pair: 24 FFMA2 + 16 FMNMX + 2 LDG.128.
__global__ void __launch_bounds__(THREADS, 1)
nn_kernel() {
    const int b     = blockIdx.x;
    const int dir   = b / (QBLK * CHUNKS);
    const int rem   = b % (QBLK * CHUNKS);
    const int qb    = rem / CHUNKS;
    const int chunk = rem % CHUNKS;

    const int js = chunk * CPAIRS;
    const int je = (js + CPAIRS < NPAIR) ? (js + CPAIRS) : NPAIR;

    const int tgt = dir ^ 1;
    const ulonglong2* __restrict__ pA =
        reinterpret_cast<const ulonglong2*>(g_packA[tgt]);
    const ulonglong2* __restrict__ pB =
        reinterpret_cast<const ulonglong2*>(g_packB[tgt]);

    // Per-thread query state: negated components, splat into both f32x2 lanes.
    unsigned long long nqx[QPT], nqy[QPT], nqz[QPT];
    #pragma unroll
    for (int k = 0; k < QPT; ++k) {
        int qi = qb * QPB + k * THREADS + threadIdx.x;
        float4 q = g_q[dir][qi];
        nqx[k] = pack2(-q.x, -q.x);
        nqy[k] = pack2(-q.y, -q.y);
        nqz[k] = pack2(-q.z, -q.z);
    }

    float m0[QPT], m1[QPT];
    #pragma unroll
    for (int k = 0; k < QPT; ++k) { m0[k] = 3.0e38f; m1[k] = 3.0e38f; }

    // Register double-buffer: prefetch next target pair one iteration ahead.
    ulonglong2 A = pA[js];
    ulonglong2 B = pB[js];

    for (int j = js; j < je; ++j) {
        // Prefetch next (clamped so the last iteration stays in bounds).
        int jn = (j + 1 < je) ? (j + 1) : js;
        ulonglong2 An = pA[jn];
        ulonglong2 Bn = pB[jn];

        #pragma unroll
        for (int k = 0; k < QPT; ++k) {
            // score = w - q.b   (argmin-equivalent to ||q-b||^2), 2 targets at once
            unsigned long long acc = fma2(nqz[k], B.x, B.y);
            acc = fma2(nqy[k], A.y, acc);
            acc = fma2(nqx[k], A.x, acc);
            float2 s = *reinterpret_cast<float2*>(&acc);
            m0[k] = fminf(m0[k], s.x);
            m1[k] = fminf(m1[k], s.y);
        }

        A = An; B = Bn;
    }

    #pragma unroll
    for (int k = 0; k < QPT; ++k) {
        int qi = qb * QPB + k * THREADS + threadIdx.x;
        float s = fminf(m0[k], m1[k]);
        atomicMin(&g_minbits[dir][qi], enc_f32(s));
    }
}

__global__ void __launch_bounds__(256)
reduce_kernel(float* __restrict__ out) {
    const int i   = blockIdx.x * blockDim.x + threadIdx.x;   // 0 .. 32767
    const int dir = i >> 14;
    const int qi  = i & (NPTS - 1);

    float s  = dec_f32(g_minbits[dir][qi]);
    float qw = g_q[dir][qi].w;
    float d2 = 2.0f * (qw + s);
    float d  = sqrtf(fmaxf(d2, 0.0f));

    __shared__ float warp_sums[8];
    float v = d;
    #pragma unroll
    for (int off = 16; off > 0; off >>= 1)
        v += __shfl_xor_sync(0xFFFFFFFFu, v, off);
    const int lane = threadIdx.x & 31;
    const int wid  = threadIdx.x >> 5;
    if (lane == 0) warp_sums[wid] = v;
    __syncthreads();
    if (wid == 0) {
        float t = (lane < 8) ? warp_sums[lane] : 0.0f;
        #pragma unroll
        for (int off = 4; off > 0; off >>= 1)
            t += __shfl_xor_sync(0xFFFFFFFFu, t, off);
        if (lane == 0)
            atomicAdd(out, t * (1.0f / (float)NPTS));
    }
}

extern "C" void kernel_launch(void* const* d_in, const int* in_sizes, int n_in,
                              void* d_out, int out_size) {
    const float* pc1 = (const float*)d_in[0];
    const float* pc2 = (const float*)d_in[1];
    float* out = (float*)d_out;

    prep_kernel<<<(2 * NPAIR + 255) / 256, 256>>>(pc1, pc2, out);
    nn_kernel<<<2 * QBLK * CHUNKS, THREADS>>>();
    reduce_kernel<<<(2 * NPTS) / 256, 256>>>(out);
}